// round 1
// baseline (speedup 1.0000x reference)
#include <cuda_runtime.h>
#include <stdint.h>
#include <math.h>

#define ND 96      // node dim
#define ED 64      // edge dim
#define KD 256     // in dim
#define TE 32      // edges per tile
#define BLK 384    // threads per block
#define MAXN (1<<17)

typedef unsigned long long u64t;

__device__ float g_cnt[MAXN];
__device__ int g_is64;

__device__ __forceinline__ uint32_t smem_u32(const void* p) {
    uint32_t r;
    asm("{ .reg .u64 t; cvta.to.shared.u64 t, %1; cvt.u32.u64 %0, t; }"
        : "=r"(r) : "l"(p));
    return r;
}

__global__ void init_kernel(float* __restrict__ out, const uint32_t* __restrict__ ew,
                            long long total, int n, long long nwords) {
    long long i = (long long)blockIdx.x * blockDim.x + threadIdx.x;
    if (i < total) out[i] = 0.0f;
    if (i < n) g_cnt[i] = 0.0f;
    if (i == 0) {
        // int64 vs int32 edge_index detection: for int64 (values < 2^31),
        // every odd 32-bit word (high half) is zero.
        int is64 = 1;
        long long m = nwords < 256 ? nwords : 256;
        for (long long w = 1; w < m; w += 2)
            if (ew[w] != 0u) { is64 = 0; break; }
        g_is64 = is64;
    }
}

__global__ __launch_bounds__(BLK, 1)
void edge_kernel(const float* __restrict__ h,
                 const void* __restrict__ eidx,
                 const float* __restrict__ edge_attr,
                 const float* __restrict__ W_e, const float* __restrict__ b_e,
                 const float* __restrict__ W_n, const float* __restrict__ b_n,
                 float* __restrict__ out, int E, int ntiles) {
    extern __shared__ float smem[];
    float* sW = smem;                 // KD*2*ND floats: [k][2j]=We[k][j], [k][2j+1]=Wn[k][j]
    float* sx = smem + KD * 2 * ND;   // KD*TE floats, 128B rows, chunk-swizzled; reused as redbuf/gbuf
    int*   sI = (int*)(sx + KD * TE); // [2*TE]: src[0:TE), dst[TE:2TE)

    const int tid = threadIdx.x;
    const int j   = tid % ND;         // output column
    const int sub = tid / ND;         // 0..3
    const int g   = sub & 1;          // edge half: edges [16g, 16g+16)
    const int kh  = sub >> 1;         // k half:    k in [128*kh, 128*kh+128)
    const int tid0 = g * ND + j;      // 0..191

    // Load both weight matrices into smem, interleaved per (k,j).
    for (int idx = tid; idx < KD * ND; idx += BLK) {
        int k = idx / ND, c = idx % ND;
        sW[k * 2 * ND + 2 * c]     = W_e[idx];
        sW[k * 2 * ND + 2 * c + 1] = W_n[idx];
    }

    const int is64 = g_is64;
    const long long* e64 = (const long long*)eidx;
    const int*       e32 = (const int*)eidx;

    const uint32_t sx_b = smem_u32(sx);
    const float be = b_e[j], bn = b_n[j];

    u64t*  redbuf = (u64t*)sx;
    float* gbuf   = sx;

    for (int t = blockIdx.x; t < ntiles; t += gridDim.x) {
        long long ebase = (long long)t * TE;
        __syncthreads();  // sx/sI free from previous tile (and covers W-load on iter 0)

        if (tid < 2 * TE) {
            int which = tid >> 5;  // 0 = src, 1 = dst (TE == 32)
            int e = tid & 31;
            long long eg = ebase + e;
            int v = -1;
            if (eg < (long long)E) {
                long long pos = (long long)which * E + eg;
                v = is64 ? (int)e64[pos] : e32[pos];
            }
            sI[tid] = v;
        }
        __syncthreads();

        // Stage x[e][k] into swizzled smem rows (row = 32 floats = 128B).
        #pragma unroll 4
        for (int idx = tid; idx < TE * KD; idx += BLK) {
            int e = idx >> 8;
            int k = idx & (KD - 1);
            float v = 0.0f;
            int src = sI[e];
            if (src >= 0) {
                if (k < ND)            v = h[(long long)src * ND + k];
                else if (k < 2 * ND)   v = h[(long long)sI[TE + e] * ND + (k - ND)];
                else                   v = edge_attr[ebase * ED + (long long)e * ED + (k - 2 * ND)];
            }
            int chunk = (e >> 2) ^ (k & 7);
            sx[k * TE + chunk * 4 + (e & 3)] = v;
        }
        __syncthreads();

        // Main GEMM fragment: acc[a] covers edges (16g+2a, 16g+2a+1), both matrices,
        // partial over this thread's k-half. Packed f32x2 FMAs.
        u64t aE[8], aN[8];
        #pragma unroll
        for (int a = 0; a < 8; a++) { aE[a] = 0ull; aN[a] = 0ull; }

        const float* wp = sW + 2 * j + (kh * 128) * (2 * ND);
        const uint32_t xb = sx_b + (uint32_t)(kh * 128) * (TE * 4);
        #pragma unroll 4
        for (int kk = 0; kk < 128; kk++) {
            float2 w = *(const float2*)(wp + kk * 2 * ND);
            u64t we2, wn2;
            asm("mov.b64 %0, {%1,%1};" : "=l"(we2) : "r"(__float_as_uint(w.x)));
            asm("mov.b64 %0, {%1,%1};" : "=l"(wn2) : "r"(__float_as_uint(w.y)));
            int sw = kk & 7;  // (kh*128 + kk) & 7 == kk & 7
            uint32_t rowb = xb + (uint32_t)kk * (TE * 4);
            #pragma unroll
            for (int i2 = 0; i2 < 4; i2++) {
                int chunk = (4 * g + i2) ^ sw;
                u64t x01, x23;
                asm("ld.shared.v2.b64 {%0,%1}, [%2];"
                    : "=l"(x01), "=l"(x23) : "r"(rowb + (uint32_t)chunk * 16));
                asm("fma.rn.f32x2 %0, %1, %2, %0;" : "+l"(aE[2 * i2])     : "l"(x01), "l"(we2));
                asm("fma.rn.f32x2 %0, %1, %2, %0;" : "+l"(aE[2 * i2 + 1]) : "l"(x23), "l"(we2));
                asm("fma.rn.f32x2 %0, %1, %2, %0;" : "+l"(aN[2 * i2])     : "l"(x01), "l"(wn2));
                asm("fma.rn.f32x2 %0, %1, %2, %0;" : "+l"(aN[2 * i2 + 1]) : "l"(x23), "l"(wn2));
            }
        }

        __syncthreads();  // x reads done; sx reusable as reduction buffer
        if (kh == 1) {
            #pragma unroll
            for (int a = 0; a < 8; a++) {
                redbuf[a * 192 + tid0]       = aE[a];
                redbuf[(8 + a) * 192 + tid0] = aN[a];
            }
        }
        __syncthreads();

        float gv[16];
        if (kh == 0) {
            #pragma unroll
            for (int a = 0; a < 8; a++) {
                u64t pe = redbuf[a * 192 + tid0];
                u64t pn = redbuf[(8 + a) * 192 + tid0];
                asm("add.rn.f32x2 %0, %0, %1;" : "+l"(aE[a]) : "l"(pe));
                asm("add.rn.f32x2 %0, %0, %1;" : "+l"(aN[a]) : "l"(pn));
                uint32_t el, eh, nl, nh;
                asm("mov.b64 {%0,%1}, %2;" : "=r"(el), "=r"(eh) : "l"(aE[a]));
                asm("mov.b64 {%0,%1}, %2;" : "=r"(nl), "=r"(nh) : "l"(aN[a]));
                float se0 = __uint_as_float(el) + be;
                float se1 = __uint_as_float(eh) + be;
                float sn0 = __uint_as_float(nl) + bn;
                float sn1 = __uint_as_float(nh) + bn;
                float g0 = 1.0f / (1.0f + expf(-se0));
                float g1 = 1.0f / (1.0f + expf(-se1));
                float m0 = fmaxf(sn0, 0.0f) + log1pf(expf(-fabsf(sn0)));
                float m1 = fmaxf(sn1, 0.0f) + log1pf(expf(-fabsf(sn1)));
                gv[2 * a]     = g0 * m0;
                gv[2 * a + 1] = g1 * m1;
            }
        }
        __syncthreads();  // all redbuf reads done before gbuf overwrites it
        if (kh == 0) {
            #pragma unroll
            for (int a = 0; a < 8; a++) {
                int e = 16 * g + 2 * a;
                gbuf[e * ND + j]       = gv[2 * a];
                gbuf[(e + 1) * ND + j] = gv[2 * a + 1];
            }
        }
        __syncthreads();

        // Scatter: 32 edges x 96 cols as float2 vector reductions.
        for (int q = tid; q < TE * ND / 2; q += BLK) {
            int e = q / (ND / 2);
            int c = (q % (ND / 2)) * 2;
            int dst = sI[TE + e];
            if (dst >= 0) {
                float2 v = *(const float2*)(gbuf + e * ND + c);
                float* addr = out + (long long)dst * ND + c;
                asm volatile("red.global.add.v2.f32 [%0], {%1,%2};"
                             :: "l"(addr), "f"(v.x), "f"(v.y) : "memory");
            }
        }
        if (tid < TE) {
            int dst = sI[TE + tid];
            if (dst >= 0) atomicAdd(&g_cnt[dst], 1.0f);
        }
    }
}

__global__ void finalize_kernel(const float* __restrict__ h, float* __restrict__ out,
                                long long total) {
    long long i = (long long)blockIdx.x * blockDim.x + threadIdx.x;
    if (i < total) {
        int node = (int)(i / ND);
        float c = g_cnt[node];
        c = c < 1.0f ? 1.0f : c;
        out[i] = h[i] + out[i] / c;
    }
}

extern "C" void kernel_launch(void* const* d_in, const int* in_sizes, int n_in,
                              void* d_out, int out_size) {
    const float* h   = (const float*)d_in[0];
    const void*  ei  = d_in[1];
    const float* ea  = (const float*)d_in[2];
    const float* W_e = (const float*)d_in[3];
    const float* b_e = (const float*)d_in[4];
    const float* W_n = (const float*)d_in[5];
    const float* b_n = (const float*)d_in[6];
    float* out = (float*)d_out;

    int N = in_sizes[0] / ND;
    int E = in_sizes[2] / ED;
    long long total  = (long long)N * ND;
    long long nwords = (long long)in_sizes[1];  // >= 2E 32-bit words either way

    int ib = (int)((total + 255) / 256);
    init_kernel<<<ib, 256>>>(out, (const uint32_t*)ei, total, N, nwords);

    int ntiles = (E + TE - 1) / TE;
    size_t shmem = (size_t)(KD * 2 * ND + KD * TE) * sizeof(float) + 2 * TE * sizeof(int);
    cudaFuncSetAttribute(edge_kernel, cudaFuncAttributeMaxDynamicSharedMemorySize, (int)shmem);
    int grid = 148 * 4;
    if (grid > ntiles) grid = ntiles;
    edge_kernel<<<grid, BLK, shmem>>>(h, ei, ea, W_e, b_e, W_n, b_n, out, E, ntiles);

    finalize_kernel<<<ib, 256>>>(h, out, total);
}